// round 1
// baseline (speedup 1.0000x reference)
#include <cuda_runtime.h>

// Problem constants
#define NB   32      // batch
#define NN   1024    // nodes per graph
#define NF   128     // in features
#define NH   128     // hidden / out features

// Scratch for support = x @ W  (16 MB, static device array -> allocation-guard safe)
__device__ float g_support[(size_t)NB * NN * NH];

// ---------------------------------------------------------------------------
// Register-tiled fp32 GEMM:  C[b] = A[b] (M x K) * B[b] (K x NH)  (+bias, relu)
//   BM=64, BN=128, BK=16, 128 threads, 8x8 micro-tile per thread.
//   K is a template param (128 or 1024), both divisible by BK; M=1024 divisible
//   by BM; no bounds checks needed.
// ---------------------------------------------------------------------------
template <int K, bool RELU_BIAS>
__global__ __launch_bounds__(128, 4)
void gcn_gemm_kernel(const float* __restrict__ A, long strideA,
                     const float* __restrict__ Bm, long strideB,
                     float* __restrict__ C,
                     const float* __restrict__ bias)
{
    constexpr int BM = 64, BN = 128, BK = 16;

    __shared__ float As[BK][BM];      // k-major
    __shared__ float Bs[BK][BN];

    const int batch   = blockIdx.y;
    const int rowTile = blockIdx.x;

    const float* Ab = A  + (size_t)batch * strideA + (size_t)rowTile * BM * K;
    const float* Bb = Bm + (size_t)batch * strideB;

    const int tid  = threadIdx.x;
    const int tcol = tid & 15;        // 16 thread-cols * 8 = 128 cols
    const int trow = tid >> 4;        // 8 thread-rows * 8 = 64 rows

    float acc[8][8];
    #pragma unroll
    for (int i = 0; i < 8; i++)
        #pragma unroll
        for (int j = 0; j < 8; j++) acc[i][j] = 0.0f;

    for (int k0 = 0; k0 < K; k0 += BK) {
        // ---- Load A tile (64 x 16) : 2 coalesced float4 per thread ----
        #pragma unroll
        for (int s = 0; s < 2; s++) {
            int p  = s * 128 + tid;          // 0..255 float4 slots
            int r  = p >> 2;                 // row in tile (0..63)
            int k4 = (p & 3) * 4;            // k offset (0,4,8,12)
            float4 v = *reinterpret_cast<const float4*>(Ab + (size_t)r * K + k0 + k4);
            As[k4 + 0][r] = v.x;
            As[k4 + 1][r] = v.y;
            As[k4 + 2][r] = v.z;
            As[k4 + 3][r] = v.w;
        }
        // ---- Load B tile (16 x 128) : 4 coalesced float4 per thread ----
        #pragma unroll
        for (int s = 0; s < 4; s++) {
            int p  = s * 128 + tid;          // 0..511 float4 slots
            int r  = p >> 5;                 // k row (0..15)
            int c4 = (p & 31) * 4;           // col (0..124 step 4)
            *reinterpret_cast<float4*>(&Bs[r][c4]) =
                *reinterpret_cast<const float4*>(Bb + (size_t)(k0 + r) * NH + c4);
        }
        __syncthreads();

        // ---- Compute: 16 k-steps x 64 FMA ----
        #pragma unroll
        for (int k = 0; k < BK; k++) {
            float a[8], bv[8];
            *reinterpret_cast<float4*>(&a[0])  = *reinterpret_cast<float4*>(&As[k][trow * 8]);
            *reinterpret_cast<float4*>(&a[4])  = *reinterpret_cast<float4*>(&As[k][trow * 8 + 4]);
            *reinterpret_cast<float4*>(&bv[0]) = *reinterpret_cast<float4*>(&Bs[k][tcol * 8]);
            *reinterpret_cast<float4*>(&bv[4]) = *reinterpret_cast<float4*>(&Bs[k][tcol * 8 + 4]);
            #pragma unroll
            for (int i = 0; i < 8; i++)
                #pragma unroll
                for (int j = 0; j < 8; j++)
                    acc[i][j] = fmaf(a[i], bv[j], acc[i][j]);
        }
        __syncthreads();
    }

    // ---- Epilogue ----
    float bias_v[8];
    #pragma unroll
    for (int j = 0; j < 8; j++)
        bias_v[j] = RELU_BIAS ? bias[tcol * 8 + j] : 0.0f;

    float* Cb = C + (size_t)batch * NN * NH + (size_t)rowTile * BM * NH;
    #pragma unroll
    for (int i = 0; i < 8; i++) {
        int row = trow * 8 + i;
        float o[8];
        #pragma unroll
        for (int j = 0; j < 8; j++) {
            float v = acc[i][j] + bias_v[j];
            o[j] = RELU_BIAS ? fmaxf(v, 0.0f) : v;
        }
        *reinterpret_cast<float4*>(Cb + (size_t)row * NH + tcol * 8)     = *reinterpret_cast<float4*>(&o[0]);
        *reinterpret_cast<float4*>(Cb + (size_t)row * NH + tcol * 8 + 4) = *reinterpret_cast<float4*>(&o[4]);
    }
}

// ---------------------------------------------------------------------------
// Launch: two GEMMs back-to-back (graph-capturable, no sync, no alloc)
//   d_in[0] = x   [32,1024,128] f32
//   d_in[1] = adj [32,1024,1024] f32
//   d_in[2] = W   [128,128] f32
//   d_in[3] = b   [128] f32
//   d_out   = out [32,1024,128] f32
// ---------------------------------------------------------------------------
extern "C" void kernel_launch(void* const* d_in, const int* in_sizes, int n_in,
                              void* d_out, int out_size)
{
    const float* x   = (const float*)d_in[0];
    const float* adj = (const float*)d_in[1];
    const float* W   = (const float*)d_in[2];
    const float* b   = (const float*)d_in[3];
    float* out = (float*)d_out;

    float* support = nullptr;
    cudaGetSymbolAddress((void**)&support, g_support);

    dim3 grid(NN / 64, NB);
    dim3 block(128);

    // support = x @ W  (W shared across batch -> strideB = 0)
    gcn_gemm_kernel<NF, false><<<grid, block>>>(x, (long)NN * NF, W, 0L, support, nullptr);

    // out = relu(adj @ support + b)
    gcn_gemm_kernel<NN, true><<<grid, block>>>(adj, (long)NN * NN, support, (long)NN * NH, out, b);
}

// round 4
// speedup vs baseline: 2.3851x; 2.3851x over previous
#include <cuda_runtime.h>
#include <cuda_fp16.h>
#include <cstdint>

// Problem constants
#define NB   32      // batch
#define NN   1024    // nodes per graph
#define NF   128     // in features
#define NH   128     // hidden features

// fp32 scratch for support = x @ W (static -> allocation-guard safe)
__device__ float g_support[(size_t)NB * NN * NH];   // 16 MB

// ===========================================================================
// PTX helpers (all baseline sm_80-class instructions -> compile on compute_103)
// ===========================================================================
__device__ __forceinline__ uint32_t smem_to_u32(const void* p) {
    uint32_t a;
    asm("{ .reg .u64 t; cvta.to.shared.u64 t, %1; cvt.u32.u64 %0, t; }" : "=r"(a) : "l"(p));
    return a;
}

#define LDSM4(R, addr) \
    asm volatile("ldmatrix.sync.aligned.m8n8.x4.shared.b16 {%0,%1,%2,%3}, [%4];" \
        : "=r"((R)[0]), "=r"((R)[1]), "=r"((R)[2]), "=r"((R)[3]) : "r"(addr))

#define LDSM4T(R, addr) \
    asm volatile("ldmatrix.sync.aligned.m8n8.x4.trans.shared.b16 {%0,%1,%2,%3}, [%4];" \
        : "=r"((R)[0]), "=r"((R)[1]), "=r"((R)[2]), "=r"((R)[3]) : "r"(addr))

#define MMA16816(C, A, b0, b1) \
    asm volatile("mma.sync.aligned.m16n8k16.row.col.f32.f16.f16.f32 " \
        "{%0,%1,%2,%3},{%4,%5,%6,%7},{%8,%9},{%0,%1,%2,%3};" \
        : "+f"((C)[0]), "+f"((C)[1]), "+f"((C)[2]), "+f"((C)[3]) \
        : "r"((A)[0]), "r"((A)[1]), "r"((A)[2]), "r"((A)[3]), "r"(b0), "r"(b1))

__device__ __forceinline__ uint32_t pack_h2(__half a, __half b) {
    __half2 t = __halves2half2(a, b);
    return *reinterpret_cast<uint32_t*>(&t);
}

// fp32 -> (hi fp16, lo fp16) split of a float4
__device__ __forceinline__ void split4(float4 v, uint2& hu, uint2& lu) {
    __half h0 = __float2half_rn(v.x), h1 = __float2half_rn(v.y);
    __half h2 = __float2half_rn(v.z), h3 = __float2half_rn(v.w);
    __half l0 = __float2half_rn(v.x - __half2float(h0));
    __half l1 = __float2half_rn(v.y - __half2float(h1));
    __half l2 = __float2half_rn(v.z - __half2float(h2));
    __half l3 = __float2half_rn(v.w - __half2float(h3));
    hu.x = pack_h2(h0, h1); hu.y = pack_h2(h2, h3);
    lu.x = pack_h2(l0, l1); lu.y = pack_h2(l2, l3);
}

// ===========================================================================
// Unified split-fp16 HMMA GEMM:  C = [relu(] A(fp32, MxK) @ B(fp32, Kx128) [+bias)]
//   CTA: 128x128 tile, 256 threads = 8 warps (4m x 2n), warp tile 32x64.
//   BK=32, double-buffered smem, register-prefetch pipeline.
//   3-pass error-compensated fp16: Ah*Bh + Ah*Bl + Al*Bh, fp32 accumulate.
// ===========================================================================
#define RSA   80        // A smem row stride bytes (32+8 halves)
#define RSB   272       // B smem row stride bytes (128+8 halves)
#define OAH   0
#define OAL   10240     // 128*80
#define OBH   20480
#define OBL   29184     // +32*272
#define STAGE 37888
#define SMEMB (2*STAGE + 512)

template <int K, bool BIAS_RELU>
__global__ __launch_bounds__(256, 1)
void mma_gemm_kernel(const float* __restrict__ A, long lda, long strideAb,
                     const float* __restrict__ B, long strideBb,
                     float* __restrict__ C, long strideCb,
                     const float* __restrict__ bias)
{
    extern __shared__ char smem[];
    constexpr int NCH = K / 32;

    const int tid = threadIdx.x;
    const int l   = tid & 31;
    const int wid = tid >> 5;
    const int wm  = wid >> 1;      // 0..3
    const int wn  = wid & 1;       // 0..1

    const float* Ag = A + (size_t)blockIdx.y * strideAb + (size_t)blockIdx.x * 128 * lda;
    const float* Bg = B + (size_t)blockIdx.y * strideBb;
    float*       Cg = C + (size_t)blockIdx.y * strideCb + (size_t)blockIdx.x * 128 * NH;

    float* bias_s = reinterpret_cast<float*>(smem + 2 * STAGE);
    if (BIAS_RELU && tid < NH) bias_s[tid] = bias[tid];

    const uint32_t sb = smem_to_u32(smem);

    float c[2][8][4];
    #pragma unroll
    for (int i = 0; i < 2; i++)
        #pragma unroll
        for (int j = 0; j < 8; j++)
            #pragma unroll
            for (int q = 0; q < 4; q++) c[i][j][q] = 0.0f;

    float4 pa[4], pb[4];    // register prefetch for one 128x32 A + 32x128 B chunk

    auto loadA = [&](int k0) {
        #pragma unroll
        for (int s = 0; s < 4; s++) {
            int f = s * 256 + tid;
            int r = f >> 3, c4 = f & 7;
            pa[s] = *reinterpret_cast<const float4*>(Ag + (size_t)r * lda + k0 + c4 * 4);
        }
    };
    auto loadB = [&](int k0) {
        #pragma unroll
        for (int s = 0; s < 4; s++) {
            int f = s * 256 + tid;
            int r = f >> 5, c4 = f & 31;
            pb[s] = *reinterpret_cast<const float4*>(Bg + (size_t)(k0 + r) * NH + c4 * 4);
        }
    };
    auto storeStage = [&](int buf) {
        char* st = smem + buf * STAGE;
        #pragma unroll
        for (int s = 0; s < 4; s++) {
            int f = s * 256 + tid;
            int r = f >> 3, c4 = f & 7;
            uint2 hu, lu; split4(pa[s], hu, lu);
            *reinterpret_cast<uint2*>(st + OAH + r * RSA + c4 * 8) = hu;
            *reinterpret_cast<uint2*>(st + OAL + r * RSA + c4 * 8) = lu;
        }
        #pragma unroll
        for (int s = 0; s < 4; s++) {
            int f = s * 256 + tid;
            int r = f >> 5, c4 = f & 31;
            uint2 hu, lu; split4(pb[s], hu, lu);
            *reinterpret_cast<uint2*>(st + OBH + r * RSB + c4 * 8) = hu;
            *reinterpret_cast<uint2*>(st + OBL + r * RSB + c4 * 8) = lu;
        }
    };
    auto compute = [&](int buf) {
        const uint32_t stg = sb + buf * STAGE;
        #pragma unroll
        for (int ks = 0; ks < 2; ks++) {
            // A fragments (hi & lo) for both 16-row atoms of this warp
            uint32_t ar = stg + OAH + (uint32_t)(wm * 32 + (l & 15)) * RSA + ks * 32 + (l >> 4) * 16;
            uint32_t ah0[4], ah1[4], al0[4], al1[4];
            LDSM4(ah0, ar);
            LDSM4(ah1, ar + 16 * RSA);
            LDSM4(al0, ar + (OAL - OAH));
            LDSM4(al1, ar + (OAL - OAH) + 16 * RSA);
            #pragma unroll
            for (int jp = 0; jp < 4; jp++) {   // n-atom pairs (n16 per ldmatrix.x4)
                uint32_t br = stg + OBH + (uint32_t)(ks * 16 + (l & 15)) * RSB
                            + (uint32_t)(wn * 64 + jp * 16 + (l >> 4) * 8) * 2;
                uint32_t bh[4], bl[4];
                LDSM4T(bh, br);
                LDSM4T(bl, br + (OBL - OBH));
                #pragma unroll
                for (int jj = 0; jj < 2; jj++) {
                    const int j = jp * 2 + jj;
                    MMA16816(c[0][j], ah0, bh[2*jj], bh[2*jj+1]);   // hh
                    MMA16816(c[1][j], ah1, bh[2*jj], bh[2*jj+1]);
                    MMA16816(c[0][j], ah0, bl[2*jj], bl[2*jj+1]);   // hl
                    MMA16816(c[1][j], ah1, bl[2*jj], bl[2*jj+1]);
                    MMA16816(c[0][j], al0, bh[2*jj], bh[2*jj+1]);   // lh
                    MMA16816(c[1][j], al1, bh[2*jj], bh[2*jj+1]);
                }
            }
        }
    };

    // -------- pipeline --------
    loadA(0); loadB(0);
    storeStage(0);
    __syncthreads();

    for (int ch = 0; ch < NCH; ch++) {
        if (ch + 1 < NCH) { loadA((ch + 1) * 32); loadB((ch + 1) * 32); }
        compute(ch & 1);
        __syncthreads();
        if (ch + 1 < NCH) {
            storeStage((ch + 1) & 1);
            __syncthreads();
        }
    }

    // -------- epilogue --------
    #pragma unroll
    for (int i = 0; i < 2; i++) {
        const int r0 = wm * 32 + i * 16 + (l >> 2);
        #pragma unroll
        for (int j = 0; j < 8; j++) {
            const int col = wn * 64 + j * 8 + (l & 3) * 2;
            float2 v0 = make_float2(c[i][j][0], c[i][j][1]);
            float2 v1 = make_float2(c[i][j][2], c[i][j][3]);
            if (BIAS_RELU) {
                const float b0 = bias_s[col], b1 = bias_s[col + 1];
                v0.x = fmaxf(v0.x + b0, 0.0f); v0.y = fmaxf(v0.y + b1, 0.0f);
                v1.x = fmaxf(v1.x + b0, 0.0f); v1.y = fmaxf(v1.y + b1, 0.0f);
            }
            *reinterpret_cast<float2*>(Cg + (size_t)r0 * NH + col)       = v0;
            *reinterpret_cast<float2*>(Cg + (size_t)(r0 + 8) * NH + col) = v1;
        }
    }
}

// ===========================================================================
// Launch: GEMM-1 (x@W -> support, fp32) then GEMM-2 (relu(adj@support + b))
// ===========================================================================
extern "C" void kernel_launch(void* const* d_in, const int* in_sizes, int n_in,
                              void* d_out, int out_size)
{
    const float* x   = (const float*)d_in[0];
    const float* adj = (const float*)d_in[1];
    const float* W   = (const float*)d_in[2];
    const float* b   = (const float*)d_in[3];
    float* out = (float*)d_out;

    float* support = nullptr;
    cudaGetSymbolAddress((void**)&support, g_support);

    cudaFuncSetAttribute(mma_gemm_kernel<NF, false>,
                         cudaFuncAttributeMaxDynamicSharedMemorySize, SMEMB);
    cudaFuncSetAttribute(mma_gemm_kernel<NN, true>,
                         cudaFuncAttributeMaxDynamicSharedMemorySize, SMEMB);

    // GEMM-1: support = x @ W    (x as flat [32768, 128], W shared)
    mma_gemm_kernel<NF, false><<<dim3(NB * NN / 128, 1), 256, SMEMB>>>(
        x, NF, 0L, W, 0L, support, 0L, nullptr);

    // GEMM-2: out = relu(adj @ support + b)
    mma_gemm_kernel<NN, true><<<dim3(NN / 128, NB), 256, SMEMB>>>(
        adj, NN, (long)NN * NN, support, (long)NN * NH, out, (long)NN * NH, b);
}